// round 7
// baseline (speedup 1.0000x reference)
#include <cuda_runtime.h>
#include <cuda_bf16.h>
#include <stdint.h>

// DayAdapter via tf32 mma.sync: y = softsign(x + x@E + b), E = W - I (|E|~0.02).
// CTA 256x128, warp tile 64x64 (CUTLASS sm80 shape): LDSM:MMA = 0.25,
// 3-stage cp.async pipeline, register fragment pipelining, 1 CTA/SM.

#define DIMK 512
#define TOK  1024
#define NB   64
#define NDAYS 24

#define CTA_M 256
#define CTA_N 128
#define BK    32
#define KSTEPS (DIMK / BK)       // 16
#define NTHREADS 256             // 8 warps: 4(m) x 2(n), warp tile 64x64
#define STAGES 3

// Stage: A 256x32 f32 (32KB) | B 128x32 f32 (16KB); rows 128B = 8 x 16B chunks
#define STG_BYTES 49152
#define OFF_A 0
#define OFF_B 32768
#define SMEM_TOTAL (STAGES * STG_BYTES)   // 147456

__device__ float g_Et[(size_t)NDAYS * DIMK * DIMK];   // E^T [day][n][k], tf32-rounded

// ---------------- helpers ----------------
__device__ __forceinline__ uint32_t smem_u32(const void* p) {
    return (uint32_t)__cvta_generic_to_shared(p);
}
__device__ __forceinline__ uint32_t swz(uint32_t row, uint32_t ch) {
    return row * 128u + ((ch ^ (row & 7u)) << 4);
}
__device__ __forceinline__ void ldsm_x4(uint32_t* r, uint32_t addr) {
    asm volatile("ldmatrix.sync.aligned.m8n8.x4.shared.b16 {%0,%1,%2,%3}, [%4];"
                 : "=r"(r[0]), "=r"(r[1]), "=r"(r[2]), "=r"(r[3]) : "r"(addr));
}
__device__ __forceinline__ void mma_tf32(float* c, const uint32_t* a, uint32_t b0, uint32_t b1) {
    asm volatile(
        "mma.sync.aligned.m16n8k8.row.col.f32.tf32.tf32.f32 "
        "{%0,%1,%2,%3}, {%4,%5,%6,%7}, {%8,%9}, {%0,%1,%2,%3};"
        : "+f"(c[0]), "+f"(c[1]), "+f"(c[2]), "+f"(c[3])
        : "r"(a[0]), "r"(a[1]), "r"(a[2]), "r"(a[3]), "r"(b0), "r"(b1));
}
__device__ __forceinline__ uint32_t f2tf32(uint32_t v) {
    uint32_t o;
    asm("cvt.rna.tf32.f32 %0, %1;" : "=r"(o) : "r"(v));
    return o;
}
__device__ __forceinline__ void cp_async16(uint32_t dst, const void* src) {
    asm volatile("cp.async.cg.shared.global [%0], [%1], 16;" :: "r"(dst), "l"(src));
}
__device__ __forceinline__ void cp_commit() { asm volatile("cp.async.commit_group;"); }
__device__ __forceinline__ void cp_wait1()  { asm volatile("cp.async.wait_group 1;"); }

// ---------------- prep: Et[d][n][k] = tf32_rna(W[d][k][n] - (k==n)) ----------------
__global__ void prep_e_kernel(const float* __restrict__ W) {
    __shared__ float t[32][33];
    const int d  = blockIdx.z;
    const int k0 = blockIdx.y * 32;
    const int n0 = blockIdx.x * 32;
    const float* Wd = W + (size_t)d * DIMK * DIMK;
    #pragma unroll
    for (int i = threadIdx.y; i < 32; i += 8)
        t[i][threadIdx.x] = Wd[(size_t)(k0 + i) * DIMK + n0 + threadIdx.x];
    __syncthreads();
    #pragma unroll
    for (int i = threadIdx.y; i < 32; i += 8) {
        const int k = k0 + threadIdx.x;
        const int n = n0 + i;
        float v = t[threadIdx.x][i] - ((k == n) ? 1.0f : 0.0f);
        uint32_t r = f2tf32(__float_as_uint(v));
        g_Et[((size_t)d * DIMK + n) * DIMK + k] = __uint_as_float(r);
    }
}

// ---------------- main ----------------
__global__ void __launch_bounds__(NTHREADS, 1)
day_adapter_tf32(const float* __restrict__ x,
                 const int*   __restrict__ day_w,
                 const float* __restrict__ bias,
                 float*       __restrict__ out)
{
    extern __shared__ char smem[];
    const uint32_t sb = smem_u32(smem);
    const int tid  = threadIdx.x;
    const int wid  = tid >> 5;
    const int lane = tid & 31;

    const int n0   = blockIdx.x * CTA_N;
    const int m0   = blockIdx.y * CTA_M;
    const int bidx = blockIdx.z;

    // robust day_ids decode (int32 vs int64 buffer)
    int is64 = 1;
    #pragma unroll 8
    for (int i = 1; i < 64; i += 2)
        if (__ldg(day_w + i) != 0) is64 = 0;
    const int day = is64 ? __ldg(day_w + 2 * bidx) : __ldg(day_w + bidx);

    // -------- stage loaders --------
    // A: thread t -> row t (256 rows), full 128B row = 8 chunks
    const float* agp = x + ((size_t)bidx * TOK + m0 + tid) * DIMK;
    // B: thread t -> row t>>1 (128 rows), chunks (t&1)*4 .. +3
    const int brow = tid >> 1;
    const int bc0  = (tid & 1) * 4;
    const float* bgp = g_Et + ((size_t)day * DIMK + n0 + brow) * DIMK + bc0 * 4;

    auto LOAD_STAGE = [&](uint32_t stg, int s) {
        const float* asrc = agp + s * BK;
        #pragma unroll
        for (int c = 0; c < 8; c++)
            cp_async16(stg + OFF_A + swz(tid, c), asrc + c * 4);
        const float* bsrc = bgp + s * BK;
        #pragma unroll
        for (int c = 0; c < 4; c++)
            cp_async16(stg + OFF_B + swz(brow, bc0 + c), bsrc + c * 4);
    };

    // -------- warp tile: 4(m) x 2(n), 64x64 --------
    const int mw = (wid >> 1) * 64;
    const int nw = (wid & 1) * 64;

    float acc[4][8][4];
    #pragma unroll
    for (int i = 0; i < 4; i++)
        #pragma unroll
        for (int j = 0; j < 8; j++)
            #pragma unroll
            for (int q = 0; q < 4; q++) acc[i][j][q] = 0.0f;

    // ldmatrix lane addressing
    const int a_row = mw + (lane & 15);                       // + mt*16
    const int a_ch  = lane >> 4;                              // + 2*k2
    const int b_row = nw + (lane & 7) + ((lane >> 4) << 3);   // + np*16
    const int b_ch  = (lane >> 3) & 1;                        // + 2*k2

    // -------- prolog --------
    LOAD_STAGE(sb + 0 * STG_BYTES, 0); cp_commit();
    LOAD_STAGE(sb + 1 * STG_BYTES, 1); cp_commit();

    int slotC = 0;
    int slotP = 2;

    // -------- main loop --------
    #pragma unroll 1
    for (int s = 0; s < KSTEPS; s++) {
        cp_wait1();
        __syncthreads();

        const uint32_t stgA = sb + slotC * STG_BYTES + OFF_A;
        const uint32_t stgB = sb + slotC * STG_BYTES + OFF_B;

        // fragment buffers: B double-buffered per k2 (4 ldsm = 16 regs each),
        // A double-buffered per mt (4 regs each)
        uint32_t bf[2][16];
        uint32_t af[2][4];

        // preload k2=0 fragments
        #pragma unroll
        for (int np = 0; np < 4; np++)
            ldsm_x4(bf[0] + np * 4, stgB + swz(b_row + np * 16, b_ch));
        ldsm_x4(af[0], stgA + swz(a_row, a_ch));

        // issue next-stage global loads (overlap with MMAs)
        if (s + 2 < KSTEPS) LOAD_STAGE(sb + slotP * STG_BYTES, s + 2);
        cp_commit();

        int ab = 0;
        #pragma unroll
        for (int k2 = 0; k2 < 4; k2++) {
            const int cur = k2 & 1;
            if (k2 < 3) {
                #pragma unroll
                for (int np = 0; np < 4; np++)
                    ldsm_x4(bf[cur ^ 1] + np * 4,
                            stgB + swz(b_row + np * 16, 2 * (k2 + 1) + b_ch));
            }
            #pragma unroll
            for (int mt = 0; mt < 4; mt++) {
                if (mt < 3)
                    ldsm_x4(af[ab ^ 1], stgA + swz(a_row + (mt + 1) * 16, 2 * k2 + a_ch));
                else if (k2 < 3)
                    ldsm_x4(af[ab ^ 1], stgA + swz(a_row, 2 * (k2 + 1) + a_ch));
                #pragma unroll
                for (int nt = 0; nt < 8; nt++)
                    mma_tf32(acc[mt][nt], af[ab],
                             bf[cur][(nt >> 1) * 4 + (nt & 1) * 2],
                             bf[cur][(nt >> 1) * 4 + (nt & 1) * 2 + 1]);
                ab ^= 1;
            }
        }

        slotC = (slotC == STAGES - 1) ? 0 : slotC + 1;
        slotP = (slotP == STAGES - 1) ? 0 : slotP + 1;
    }

    // -------- epilogue: y = x + acc + bias; softsign --------
    const int r  = lane >> 2;
    const int cq = (lane & 3) * 2;
    const float* xep = x + (size_t)bidx * TOK * DIMK;
    const float* bp  = bias + (size_t)day * DIMK;

    #pragma unroll
    for (int nt = 0; nt < 8; nt++) {
        const int n = n0 + nw + nt * 8 + cq;
        const float2 bb = *(const float2*)(bp + n);
        #pragma unroll
        for (int mt = 0; mt < 4; mt++) {
            const int m = m0 + mw + mt * 16 + r;
            const float2 x0 = __ldg((const float2*)(xep + (size_t)m * DIMK + n));
            const float2 x1 = __ldg((const float2*)(xep + (size_t)(m + 8) * DIMK + n));
            float y0 = acc[mt][nt][0] + x0.x + bb.x;
            float y1 = acc[mt][nt][1] + x0.y + bb.y;
            float y2 = acc[mt][nt][2] + x1.x + bb.x;
            float y3 = acc[mt][nt][3] + x1.y + bb.y;
            float2 o0, o1;
            o0.x = __fdividef(y0, 1.0f + fabsf(y0));
            o0.y = __fdividef(y1, 1.0f + fabsf(y1));
            o1.x = __fdividef(y2, 1.0f + fabsf(y2));
            o1.y = __fdividef(y3, 1.0f + fabsf(y3));
            *(float2*)(out + (size_t)bidx * TOK * DIMK + (size_t)m * DIMK + n)       = o0;
            *(float2*)(out + (size_t)bidx * TOK * DIMK + (size_t)(m + 8) * DIMK + n) = o1;
        }
    }
}

// ---------------- launch ----------------
extern "C" void kernel_launch(void* const* d_in, const int* in_sizes, int n_in,
                              void* d_out, int out_size)
{
    const float* x   = (const float*)d_in[0];
    const int*   day = (const int*)  d_in[1];
    const float* W   = (const float*)d_in[2];
    const float* b   = (const float*)d_in[3];
    float*       out = (float*)d_out;

    cudaFuncSetAttribute(day_adapter_tf32,
                         cudaFuncAttributeMaxDynamicSharedMemorySize, SMEM_TOTAL);

    prep_e_kernel<<<dim3(DIMK / 32, DIMK / 32, NDAYS), dim3(32, 8)>>>(W);

    dim3 grid(DIMK / CTA_N, TOK / CTA_M, NB);   // (4, 4, 64) = 1024 CTAs
    day_adapter_tf32<<<grid, NTHREADS, SMEM_TOTAL>>>(x, day, b, out);
}

// round 8
// speedup vs baseline: 1.2563x; 1.2563x over previous
#include <cuda_runtime.h>
#include <cuda_bf16.h>
#include <stdint.h>

// DayAdapter via tf32 mma.sync: y = softsign(x + x@E + b), E = W - I (|E|~0.02).
// R6 base (128x128 CTA, 64x32 warp tile, 3-stage cp.async, 2 CTAs/SM) +
// per-warp k2 phase rotation to desynchronize smem crossbar bursts.

#define DIMK 512
#define TOK  1024
#define NB   64
#define NDAYS 24

#define CTA_M 128
#define CTA_N 128
#define BK    32
#define KSTEPS (DIMK / BK)       // 16
#define NTHREADS 256             // 8 warps: 2(m) x 4(n), warp tile 64x32
#define STAGES 3

#define STG_BYTES 32768          // A 16KB | B 16KB, rows 128B = 8 x 16B chunks
#define OFF_A 0
#define OFF_B 16384
#define SMEM_TOTAL (STAGES * STG_BYTES)   // 98304

__device__ float g_Et[(size_t)NDAYS * DIMK * DIMK];   // E^T [day][n][k], tf32-rounded

// ---------------- helpers ----------------
__device__ __forceinline__ uint32_t smem_u32(const void* p) {
    return (uint32_t)__cvta_generic_to_shared(p);
}
__device__ __forceinline__ uint32_t swz(uint32_t row, uint32_t ch) {
    return row * 128u + ((ch ^ (row & 7u)) << 4);
}
__device__ __forceinline__ void ldsm_x4(uint32_t* r, uint32_t addr) {
    asm volatile("ldmatrix.sync.aligned.m8n8.x4.shared.b16 {%0,%1,%2,%3}, [%4];"
                 : "=r"(r[0]), "=r"(r[1]), "=r"(r[2]), "=r"(r[3]) : "r"(addr));
}
__device__ __forceinline__ void mma_tf32(float* c, const uint32_t* a, uint32_t b0, uint32_t b1) {
    asm volatile(
        "mma.sync.aligned.m16n8k8.row.col.f32.tf32.tf32.f32 "
        "{%0,%1,%2,%3}, {%4,%5,%6,%7}, {%8,%9}, {%0,%1,%2,%3};"
        : "+f"(c[0]), "+f"(c[1]), "+f"(c[2]), "+f"(c[3])
        : "r"(a[0]), "r"(a[1]), "r"(a[2]), "r"(a[3]), "r"(b0), "r"(b1));
}
__device__ __forceinline__ uint32_t f2tf32(uint32_t v) {
    uint32_t o;
    asm("cvt.rna.tf32.f32 %0, %1;" : "=r"(o) : "r"(v));
    return o;
}
__device__ __forceinline__ void cp_async16(uint32_t dst, const void* src) {
    asm volatile("cp.async.cg.shared.global [%0], [%1], 16;" :: "r"(dst), "l"(src));
}
__device__ __forceinline__ void cp_commit() { asm volatile("cp.async.commit_group;"); }
__device__ __forceinline__ void cp_wait1()  { asm volatile("cp.async.wait_group 1;"); }

// ---------------- prep: Et[d][n][k] = tf32_rna(W[d][k][n] - (k==n)) ----------------
__global__ void prep_e_kernel(const float* __restrict__ W) {
    __shared__ float t[32][33];
    const int d  = blockIdx.z;
    const int k0 = blockIdx.y * 32;
    const int n0 = blockIdx.x * 32;
    const float* Wd = W + (size_t)d * DIMK * DIMK;
    #pragma unroll
    for (int i = threadIdx.y; i < 32; i += 8)
        t[i][threadIdx.x] = Wd[(size_t)(k0 + i) * DIMK + n0 + threadIdx.x];
    __syncthreads();
    #pragma unroll
    for (int i = threadIdx.y; i < 32; i += 8) {
        const int k = k0 + threadIdx.x;
        const int n = n0 + i;
        float v = t[threadIdx.x][i] - ((k == n) ? 1.0f : 0.0f);
        uint32_t r = f2tf32(__float_as_uint(v));
        g_Et[((size_t)d * DIMK + n) * DIMK + k] = __uint_as_float(r);
    }
}

// ---------------- main ----------------
__global__ void __launch_bounds__(NTHREADS, 2)
day_adapter_tf32(const float* __restrict__ x,
                 const int*   __restrict__ day_w,
                 const float* __restrict__ bias,
                 float*       __restrict__ out)
{
    extern __shared__ char smem[];
    const uint32_t sb = smem_u32(smem);
    const int tid  = threadIdx.x;
    const int wid  = tid >> 5;
    const int lane = tid & 31;

    const int n0   = blockIdx.x * CTA_N;
    const int m0   = blockIdx.y * CTA_M;
    const int bidx = blockIdx.z;

    // robust day_ids decode (int32 vs int64 buffer)
    int is64 = 1;
    #pragma unroll 8
    for (int i = 1; i < 64; i += 2)
        if (__ldg(day_w + i) != 0) is64 = 0;
    const int day = is64 ? __ldg(day_w + 2 * bidx) : __ldg(day_w + bidx);

    // -------- stage loaders: thread t -> row=t>>1, chunks (t&1)*4 .. +3 --------
    const int lrow = tid >> 1;
    const int lc0  = (tid & 1) * 4;
    const float* agp = x    + ((size_t)bidx * TOK + m0 + lrow) * DIMK + lc0 * 4;
    const float* bgp = g_Et + ((size_t)day  * DIMK + n0 + lrow) * DIMK + lc0 * 4;
    const uint32_t lso = swz(lrow, lc0), lso1 = swz(lrow, lc0 + 1),
                   lso2 = swz(lrow, lc0 + 2), lso3 = swz(lrow, lc0 + 3);

    auto LOAD_STAGE = [&](uint32_t stg, int s) {
        const float* asrc = agp + s * BK;
        const float* bsrc = bgp + s * BK;
        cp_async16(stg + OFF_A + lso,  asrc);
        cp_async16(stg + OFF_A + lso1, asrc + 4);
        cp_async16(stg + OFF_A + lso2, asrc + 8);
        cp_async16(stg + OFF_A + lso3, asrc + 12);
        cp_async16(stg + OFF_B + lso,  bsrc);
        cp_async16(stg + OFF_B + lso1, bsrc + 4);
        cp_async16(stg + OFF_B + lso2, bsrc + 8);
        cp_async16(stg + OFF_B + lso3, bsrc + 12);
    };

    // -------- warp tile --------
    const int mw = (wid >> 2) * 64;
    const int nw = (wid & 3) * 32;
    const int kswap = (wid & 1) << 1;        // odd warps traverse k2 as 2,3,0,1

    float acc[4][4][4];
    #pragma unroll
    for (int i = 0; i < 4; i++)
        #pragma unroll
        for (int j = 0; j < 4; j++)
            #pragma unroll
            for (int q = 0; q < 4; q++) acc[i][j][q] = 0.0f;

    // ldmatrix lane addressing
    const int a_row = mw + (lane & 15);                       // + mt*16
    const int a_ch  = lane >> 4;                              // + 2*kk
    const int b_row = nw + (lane & 7) + ((lane >> 4) << 3);   // + np*16
    const int b_ch  = (lane >> 3) & 1;                        // + 2*kk

    // -------- prolog --------
    LOAD_STAGE(sb + 0 * STG_BYTES, 0); cp_commit();
    LOAD_STAGE(sb + 1 * STG_BYTES, 1); cp_commit();

    int slotC = 0;   // consume slot for stage s
    int slotP = 2;   // produce slot for stage s+2

    // -------- main loop: one barrier per stage, pipelined + phase-rotated --------
    #pragma unroll 1
    for (int s = 0; s < KSTEPS; s++) {
        cp_wait1();
        __syncthreads();

        // issue next-stage global loads first (start DRAM/L2 fetch ASAP)
        if (s + 2 < KSTEPS) LOAD_STAGE(sb + slotP * STG_BYTES, s + 2);
        cp_commit();

        const uint32_t stg  = sb + slotC * STG_BYTES;
        const uint32_t stgA = stg + OFF_A;
        const uint32_t stgB = stg + OFF_B;

        // fragment register double buffers
        uint32_t bf[2][8];
        uint32_t af[2][4];

        // preload first k2 (= kswap) fragments
        ldsm_x4(bf[0] + 0, stgB + swz(b_row,      2 * kswap + b_ch));
        ldsm_x4(bf[0] + 4, stgB + swz(b_row + 16, 2 * kswap + b_ch));
        ldsm_x4(af[0],     stgA + swz(a_row,      2 * kswap + a_ch));

        int ab = 0;   // A-fragment buffer parity
        #pragma unroll
        for (int k2 = 0; k2 < 4; k2++) {
            const int cur = k2 & 1;
            const int kkn = (k2 + 1) ^ kswap;       // next iteration's rotated k2
            // prefetch next k2's B fragments
            if (k2 < 3) {
                ldsm_x4(bf[cur ^ 1] + 0, stgB + swz(b_row,      2 * kkn + b_ch));
                ldsm_x4(bf[cur ^ 1] + 4, stgB + swz(b_row + 16, 2 * kkn + b_ch));
            }
            const int kk = k2 ^ kswap;
            #pragma unroll
            for (int mt = 0; mt < 4; mt++) {
                // prefetch next A fragment (mt+1 of this kk, or next kk's mt=0)
                if (mt < 3)
                    ldsm_x4(af[ab ^ 1], stgA + swz(a_row + (mt + 1) * 16, 2 * kk + a_ch));
                else if (k2 < 3)
                    ldsm_x4(af[ab ^ 1], stgA + swz(a_row, 2 * kkn + a_ch));
                #pragma unroll
                for (int nt = 0; nt < 4; nt++)
                    mma_tf32(acc[mt][nt], af[ab],
                             bf[cur][(nt >> 1) * 4 + (nt & 1) * 2],
                             bf[cur][(nt >> 1) * 4 + (nt & 1) * 2 + 1]);
                ab ^= 1;
            }
        }

        slotC = (slotC == STAGES - 1) ? 0 : slotC + 1;
        slotP = (slotP == STAGES - 1) ? 0 : slotP + 1;
    }

    // -------- epilogue: y = x + acc + bias; softsign --------
    const int r  = lane >> 2;
    const int cq = (lane & 3) * 2;
    const float* xep = x + (size_t)bidx * TOK * DIMK;
    const float* bp  = bias + (size_t)day * DIMK;

    #pragma unroll
    for (int nt = 0; nt < 4; nt++) {
        const int n = n0 + nw + nt * 8 + cq;
        const float2 bb = *(const float2*)(bp + n);
        #pragma unroll
        for (int mt = 0; mt < 4; mt++) {
            const int m = m0 + mw + mt * 16 + r;
            const float2 x0 = __ldg((const float2*)(xep + (size_t)m * DIMK + n));
            const float2 x1 = __ldg((const float2*)(xep + (size_t)(m + 8) * DIMK + n));
            float y0 = acc[mt][nt][0] + x0.x + bb.x;
            float y1 = acc[mt][nt][1] + x0.y + bb.y;
            float y2 = acc[mt][nt][2] + x1.x + bb.x;
            float y3 = acc[mt][nt][3] + x1.y + bb.y;
            float2 o0, o1;
            o0.x = __fdividef(y0, 1.0f + fabsf(y0));
            o0.y = __fdividef(y1, 1.0f + fabsf(y1));
            o1.x = __fdividef(y2, 1.0f + fabsf(y2));
            o1.y = __fdividef(y3, 1.0f + fabsf(y3));
            *(float2*)(out + (size_t)bidx * TOK * DIMK + (size_t)m * DIMK + n)       = o0;
            *(float2*)(out + (size_t)bidx * TOK * DIMK + (size_t)(m + 8) * DIMK + n) = o1;
        }
    }
}

// ---------------- launch ----------------
extern "C" void kernel_launch(void* const* d_in, const int* in_sizes, int n_in,
                              void* d_out, int out_size)
{
    const float* x   = (const float*)d_in[0];
    const int*   day = (const int*)  d_in[1];
    const float* W   = (const float*)d_in[2];
    const float* b   = (const float*)d_in[3];
    float*       out = (float*)d_out;

    cudaFuncSetAttribute(day_adapter_tf32,
                         cudaFuncAttributeMaxDynamicSharedMemorySize, SMEM_TOTAL);

    prep_e_kernel<<<dim3(DIMK / 32, DIMK / 32, NDAYS), dim3(32, 8)>>>(W);

    dim3 grid(DIMK / CTA_N, TOK / CTA_M, NB);   // (4, 8, 64) = 2048 CTAs
    day_adapter_tf32<<<grid, NTHREADS, SMEM_TOTAL>>>(x, day, b, out);
}

// round 9
// speedup vs baseline: 1.3589x; 1.0816x over previous
#include <cuda_runtime.h>
#include <cuda_bf16.h>
#include <stdint.h>

// DayAdapter via tf32 mma.sync: y = softsign(x + x@E + b), E = W - I (|E|~0.02).
// R6 core (128x128 CTA, 64x32 warp tile, 3-slot cp.async ring, 2 CTAs/SM) with
// the per-stage __syncthreads replaced by an mbarrier producer/consumer pipeline
// (full[3]/empty[3], cp.async.mbarrier.arrive.noinc) so warps skew freely and
// LDSM bursts overlap MMA drains across warps.

#define DIMK 512
#define TOK  1024
#define NB   64
#define NDAYS 24

#define CTA_M 128
#define CTA_N 128
#define BK    32
#define KSTEPS (DIMK / BK)       // 16
#define NTHREADS 256             // 8 warps: 2(m) x 4(n), warp tile 64x32
#define STAGES 3

#define SM_TILES 128             // mbarriers live in [0,128)
#define STG_BYTES 32768          // A 16KB | B 16KB, rows 128B = 8 x 16B chunks
#define OFF_A 0
#define OFF_B 16384
#define SMEM_TOTAL (SM_TILES + STAGES * STG_BYTES)   // 98432

__device__ float g_Et[(size_t)NDAYS * DIMK * DIMK];   // E^T [day][n][k], tf32-rounded

// ---------------- helpers ----------------
__device__ __forceinline__ uint32_t smem_u32(const void* p) {
    return (uint32_t)__cvta_generic_to_shared(p);
}
__device__ __forceinline__ uint32_t swz(uint32_t row, uint32_t ch) {
    return row * 128u + ((ch ^ (row & 7u)) << 4);
}
__device__ __forceinline__ void ldsm_x4(uint32_t* r, uint32_t addr) {
    asm volatile("ldmatrix.sync.aligned.m8n8.x4.shared.b16 {%0,%1,%2,%3}, [%4];"
                 : "=r"(r[0]), "=r"(r[1]), "=r"(r[2]), "=r"(r[3]) : "r"(addr));
}
__device__ __forceinline__ void mma_tf32(float* c, const uint32_t* a, uint32_t b0, uint32_t b1) {
    asm volatile(
        "mma.sync.aligned.m16n8k8.row.col.f32.tf32.tf32.f32 "
        "{%0,%1,%2,%3}, {%4,%5,%6,%7}, {%8,%9}, {%0,%1,%2,%3};"
        : "+f"(c[0]), "+f"(c[1]), "+f"(c[2]), "+f"(c[3])
        : "r"(a[0]), "r"(a[1]), "r"(a[2]), "r"(a[3]), "r"(b0), "r"(b1));
}
__device__ __forceinline__ uint32_t f2tf32(uint32_t v) {
    uint32_t o;
    asm("cvt.rna.tf32.f32 %0, %1;" : "=r"(o) : "r"(v));
    return o;
}
__device__ __forceinline__ void cp_async16(uint32_t dst, const void* src) {
    asm volatile("cp.async.cg.shared.global [%0], [%1], 16;" :: "r"(dst), "l"(src));
}
__device__ __forceinline__ void cp_mbar_arrive(uint32_t mbar) {
    asm volatile("cp.async.mbarrier.arrive.noinc.shared.b64 [%0];" :: "r"(mbar) : "memory");
}
__device__ __forceinline__ void mbar_init(uint32_t addr, uint32_t cnt) {
    asm volatile("mbarrier.init.shared.b64 [%0], %1;" :: "r"(addr), "r"(cnt) : "memory");
}
__device__ __forceinline__ void mbar_arrive(uint32_t addr) {
    asm volatile("mbarrier.arrive.shared.b64 _, [%0];" :: "r"(addr) : "memory");
}
__device__ __forceinline__ void mbar_wait(uint32_t addr, uint32_t parity) {
    asm volatile(
        "{\n\t.reg .pred P;\n"
        "W%=:\n\t"
        "mbarrier.try_wait.parity.acquire.cta.shared::cta.b64 P, [%0], %1, 0x989680;\n\t"
        "@!P bra W%=;\n\t}"
        :: "r"(addr), "r"(parity) : "memory");
}

// ---------------- prep: Et[d][n][k] = tf32_rna(W[d][k][n] - (k==n)) ----------------
__global__ void prep_e_kernel(const float* __restrict__ W) {
    __shared__ float t[32][33];
    const int d  = blockIdx.z;
    const int k0 = blockIdx.y * 32;
    const int n0 = blockIdx.x * 32;
    const float* Wd = W + (size_t)d * DIMK * DIMK;
    #pragma unroll
    for (int i = threadIdx.y; i < 32; i += 8)
        t[i][threadIdx.x] = Wd[(size_t)(k0 + i) * DIMK + n0 + threadIdx.x];
    __syncthreads();
    #pragma unroll
    for (int i = threadIdx.y; i < 32; i += 8) {
        const int k = k0 + threadIdx.x;
        const int n = n0 + i;
        float v = t[threadIdx.x][i] - ((k == n) ? 1.0f : 0.0f);
        uint32_t r = f2tf32(__float_as_uint(v));
        g_Et[((size_t)d * DIMK + n) * DIMK + k] = __uint_as_float(r);
    }
}

// ---------------- main ----------------
__global__ void __launch_bounds__(NTHREADS, 2)
day_adapter_tf32(const float* __restrict__ x,
                 const int*   __restrict__ day_w,
                 const float* __restrict__ bias,
                 float*       __restrict__ out)
{
    extern __shared__ char smem[];
    const uint32_t sb = smem_u32(smem);
    const int tid  = threadIdx.x;
    const int wid  = tid >> 5;
    const int lane = tid & 31;

    const int n0   = blockIdx.x * CTA_N;
    const int m0   = blockIdx.y * CTA_M;
    const int bidx = blockIdx.z;

    // mbarriers: full[i] at sb + i*8, empty[i] at sb + 64 + i*8
    const uint32_t mb_full  = sb;
    const uint32_t mb_empty = sb + 64;
    if (tid == 0) {
        #pragma unroll
        for (int i = 0; i < STAGES; i++) {
            mbar_init(mb_full  + i * 8, NTHREADS);
            mbar_init(mb_empty + i * 8, NTHREADS);
        }
    }

    // robust day_ids decode (int32 vs int64 buffer)
    int is64 = 1;
    #pragma unroll 8
    for (int i = 1; i < 64; i += 2)
        if (__ldg(day_w + i) != 0) is64 = 0;
    const int day = is64 ? __ldg(day_w + 2 * bidx) : __ldg(day_w + bidx);

    __syncthreads();   // mbarrier init visible to all before any arrivals

    // -------- stage loaders: thread t -> row=t>>1, chunks (t&1)*4 .. +3 --------
    const int lrow = tid >> 1;
    const int lc0  = (tid & 1) * 4;
    const float* agp = x    + ((size_t)bidx * TOK + m0 + lrow) * DIMK + lc0 * 4;
    const float* bgp = g_Et + ((size_t)day  * DIMK + n0 + lrow) * DIMK + lc0 * 4;
    const uint32_t lso = swz(lrow, lc0), lso1 = swz(lrow, lc0 + 1),
                   lso2 = swz(lrow, lc0 + 2), lso3 = swz(lrow, lc0 + 3);

    auto LOAD_STAGE = [&](uint32_t stg, int s) {
        const float* asrc = agp + s * BK;
        const float* bsrc = bgp + s * BK;
        cp_async16(stg + OFF_A + lso,  asrc);
        cp_async16(stg + OFF_A + lso1, asrc + 4);
        cp_async16(stg + OFF_A + lso2, asrc + 8);
        cp_async16(stg + OFF_A + lso3, asrc + 12);
        cp_async16(stg + OFF_B + lso,  bsrc);
        cp_async16(stg + OFF_B + lso1, bsrc + 4);
        cp_async16(stg + OFF_B + lso2, bsrc + 8);
        cp_async16(stg + OFF_B + lso3, bsrc + 12);
    };

    // -------- warp tile --------
    const int mw = (wid >> 2) * 64;
    const int nw = (wid & 3) * 32;
    const int kswap = (wid & 1) << 1;        // odd warps traverse k2 as 2,3,0,1

    float acc[4][4][4];
    #pragma unroll
    for (int i = 0; i < 4; i++)
        #pragma unroll
        for (int j = 0; j < 4; j++)
            #pragma unroll
            for (int q = 0; q < 4; q++) acc[i][j][q] = 0.0f;

    // ldmatrix lane addressing
    const int a_row = mw + (lane & 15);                       // + mt*16
    const int a_ch  = lane >> 4;                              // + 2*kk
    const int b_row = nw + (lane & 7) + ((lane >> 4) << 3);   // + np*16
    const int b_ch  = (lane >> 3) & 1;                        // + 2*kk

    // -------- prolog: fill slots 0 and 1 --------
    LOAD_STAGE(sb + SM_TILES + 0 * STG_BYTES, 0);
    cp_mbar_arrive(mb_full + 0 * 8);
    LOAD_STAGE(sb + SM_TILES + 1 * STG_BYTES, 1);
    cp_mbar_arrive(mb_full + 1 * 8);

    int slotC = 0;          // consume slot (stage s)
    int slotP = 2;          // produce slot (stage s+2)
    uint32_t phF = 0;       // full-barrier phase bitmask per slot
    uint32_t phE = 0;       // empty-barrier phase bitmask per slot

    // -------- main loop: no CTA barrier, mbarrier-paced --------
    #pragma unroll 1
    for (int s = 0; s < KSTEPS; s++) {
        const uint32_t stg  = sb + SM_TILES + slotC * STG_BYTES;
        const uint32_t stgA = stg + OFF_A;
        const uint32_t stgB = stg + OFF_B;

        // consumer: wait for stage s data
        mbar_wait(mb_full + slotC * 8, (phF >> slotC) & 1);
        phF ^= 1u << slotC;

        // fragment register double buffers; preload first kk (= kswap)
        uint32_t bf[2][8];
        uint32_t af[2][4];
        ldsm_x4(bf[0] + 0, stgB + swz(b_row,      2 * kswap + b_ch));
        ldsm_x4(bf[0] + 4, stgB + swz(b_row + 16, 2 * kswap + b_ch));
        ldsm_x4(af[0],     stgA + swz(a_row,      2 * kswap + a_ch));

        // producer: refill slotP for stage s+2 (after its last readers finish)
        if (s + 2 < KSTEPS) {
            if (s > 0) {
                mbar_wait(mb_empty + slotP * 8, (phE >> slotP) & 1);
                phE ^= 1u << slotP;
            }
            LOAD_STAGE(sb + SM_TILES + slotP * STG_BYTES, s + 2);
            cp_mbar_arrive(mb_full + slotP * 8);
        }

        int ab = 0;   // A-fragment buffer parity
        #pragma unroll
        for (int k2 = 0; k2 < 4; k2++) {
            const int cur = k2 & 1;
            const int kkn = (k2 + 1) ^ kswap;       // next iteration's rotated k2
            if (k2 < 3) {
                ldsm_x4(bf[cur ^ 1] + 0, stgB + swz(b_row,      2 * kkn + b_ch));
                ldsm_x4(bf[cur ^ 1] + 4, stgB + swz(b_row + 16, 2 * kkn + b_ch));
            }
            const int kk = k2 ^ kswap;
            #pragma unroll
            for (int mt = 0; mt < 4; mt++) {
                if (mt < 3)
                    ldsm_x4(af[ab ^ 1], stgA + swz(a_row + (mt + 1) * 16, 2 * kk + a_ch));
                else if (k2 < 3)
                    ldsm_x4(af[ab ^ 1], stgA + swz(a_row, 2 * kkn + a_ch));
                #pragma unroll
                for (int nt = 0; nt < 4; nt++)
                    mma_tf32(acc[mt][nt], af[ab],
                             bf[cur][(nt >> 1) * 4 + (nt & 1) * 2],
                             bf[cur][(nt >> 1) * 4 + (nt & 1) * 2 + 1]);
                ab ^= 1;
            }
        }

        // all of this thread's LDSMs for stage s are done -> slot reusable
        mbar_arrive(mb_empty + slotC * 8);

        slotC = (slotC == STAGES - 1) ? 0 : slotC + 1;
        slotP = (slotP == STAGES - 1) ? 0 : slotP + 1;
    }

    // -------- epilogue: y = x + acc + bias; softsign --------
    const int r  = lane >> 2;
    const int cq = (lane & 3) * 2;
    const float* xep = x + (size_t)bidx * TOK * DIMK;
    const float* bp  = bias + (size_t)day * DIMK;

    #pragma unroll
    for (int nt = 0; nt < 4; nt++) {
        const int n = n0 + nw + nt * 8 + cq;
        const float2 bb = *(const float2*)(bp + n);
        #pragma unroll
        for (int mt = 0; mt < 4; mt++) {
            const int m = m0 + mw + mt * 16 + r;
            const float2 x0 = __ldg((const float2*)(xep + (size_t)m * DIMK + n));
            const float2 x1 = __ldg((const float2*)(xep + (size_t)(m + 8) * DIMK + n));
            float y0 = acc[mt][nt][0] + x0.x + bb.x;
            float y1 = acc[mt][nt][1] + x0.y + bb.y;
            float y2 = acc[mt][nt][2] + x1.x + bb.x;
            float y3 = acc[mt][nt][3] + x1.y + bb.y;
            float2 o0, o1;
            o0.x = __fdividef(y0, 1.0f + fabsf(y0));
            o0.y = __fdividef(y1, 1.0f + fabsf(y1));
            o1.x = __fdividef(y2, 1.0f + fabsf(y2));
            o1.y = __fdividef(y3, 1.0f + fabsf(y3));
            *(float2*)(out + (size_t)bidx * TOK * DIMK + (size_t)m * DIMK + n)       = o0;
            *(float2*)(out + (size_t)bidx * TOK * DIMK + (size_t)(m + 8) * DIMK + n) = o1;
        }
    }
}

// ---------------- launch ----------------
extern "C" void kernel_launch(void* const* d_in, const int* in_sizes, int n_in,
                              void* d_out, int out_size)
{
    const float* x   = (const float*)d_in[0];
    const int*   day = (const int*)  d_in[1];
    const float* W   = (const float*)d_in[2];
    const float* b   = (const float*)d_in[3];
    float*       out = (float*)d_out;

    cudaFuncSetAttribute(day_adapter_tf32,
                         cudaFuncAttributeMaxDynamicSharedMemorySize, SMEM_TOTAL);

    prep_e_kernel<<<dim3(DIMK / 32, DIMK / 32, NDAYS), dim3(32, 8)>>>(W);

    dim3 grid(DIMK / CTA_N, TOK / CTA_M, NB);   // (4, 8, 64) = 2048 CTAs
    day_adapter_tf32<<<grid, NTHREADS, SMEM_TOTAL>>>(x, day, b, out);
}

// round 10
// speedup vs baseline: 1.8589x; 1.3680x over previous
#include <cuda_runtime.h>
#include <cuda_fp16.h>
#include <stdint.h>

// DayAdapter via fp16 mma.sync m16n8k16: y = softsign(x + xh@Eh + b),
// E = W - I (|E|~0.02), xh = fp16(x), Eh = fp16(E^T). Identity term stays
// exact fp32 in the epilogue. Single fp16 GEMM: half the MMA instructions
// and half the smem bytes of the tf32 version. 4-stage mbarrier pipeline.

#define DIMK 512
#define TOK  1024
#define NB   64
#define NDAYS 24

#define CTA_M 128
#define CTA_N 128
#define BK    32
#define KSTEPS (DIMK / BK)       // 16
#define NTHREADS 256             // 8 warps: 2(m) x 4(n), warp tile 64x32
#define STAGES 4

#define SM_TILES 128             // mbarriers live in [0,128)
#define STG_BYTES 16384          // A 8KB | B 8KB, fp16 rows of 64B = 4 x 16B chunks
#define OFF_A 0
#define OFF_B 8192
#define SMEM_TOTAL (SM_TILES + STAGES * STG_BYTES)   // 65664

__device__ __half g_xh[(size_t)NB * TOK * DIMK];       // fp16(x)
__device__ __half g_Eh[(size_t)NDAYS * DIMK * DIMK];   // fp16(E^T) [day][n][k]

// ---------------- helpers ----------------
__device__ __forceinline__ uint32_t smem_u32(const void* p) {
    return (uint32_t)__cvta_generic_to_shared(p);
}
// 64B rows, 4 chunks of 16B; conflict-free: ch ^= (row>>1)&3
__device__ __forceinline__ uint32_t swz64(uint32_t row, uint32_t ch) {
    return row * 64u + ((ch ^ ((row >> 1) & 3u)) << 4);
}
__device__ __forceinline__ void ldsm_x4(uint32_t* r, uint32_t addr) {
    asm volatile("ldmatrix.sync.aligned.m8n8.x4.shared.b16 {%0,%1,%2,%3}, [%4];"
                 : "=r"(r[0]), "=r"(r[1]), "=r"(r[2]), "=r"(r[3]) : "r"(addr));
}
__device__ __forceinline__ void mma_f16(float* c, const uint32_t* a, uint32_t b0, uint32_t b1) {
    asm volatile(
        "mma.sync.aligned.m16n8k16.row.col.f32.f16.f16.f32 "
        "{%0,%1,%2,%3}, {%4,%5,%6,%7}, {%8,%9}, {%0,%1,%2,%3};"
        : "+f"(c[0]), "+f"(c[1]), "+f"(c[2]), "+f"(c[3])
        : "r"(a[0]), "r"(a[1]), "r"(a[2]), "r"(a[3]), "r"(b0), "r"(b1));
}
__device__ __forceinline__ void cp_async16(uint32_t dst, const void* src) {
    asm volatile("cp.async.cg.shared.global [%0], [%1], 16;" :: "r"(dst), "l"(src));
}
__device__ __forceinline__ void cp_mbar_arrive(uint32_t mbar) {
    asm volatile("cp.async.mbarrier.arrive.noinc.shared.b64 [%0];" :: "r"(mbar) : "memory");
}
__device__ __forceinline__ void mbar_init(uint32_t addr, uint32_t cnt) {
    asm volatile("mbarrier.init.shared.b64 [%0], %1;" :: "r"(addr), "r"(cnt) : "memory");
}
__device__ __forceinline__ void mbar_arrive(uint32_t addr) {
    asm volatile("mbarrier.arrive.shared.b64 _, [%0];" :: "r"(addr) : "memory");
}
__device__ __forceinline__ void mbar_wait(uint32_t addr, uint32_t parity) {
    asm volatile(
        "{\n\t.reg .pred P;\n"
        "W%=:\n\t"
        "mbarrier.try_wait.parity.acquire.cta.shared::cta.b64 P, [%0], %1, 0x989680;\n\t"
        "@!P bra W%=;\n\t}"
        :: "r"(addr), "r"(parity) : "memory");
}

// ---------------- prep kernels ----------------
// Eh[d][n][k] = fp16(W[d][k][n] - (k==n))
__global__ void prep_e_kernel(const float* __restrict__ W) {
    __shared__ float t[32][33];
    const int d  = blockIdx.z;
    const int k0 = blockIdx.y * 32;
    const int n0 = blockIdx.x * 32;
    const float* Wd = W + (size_t)d * DIMK * DIMK;
    #pragma unroll
    for (int i = threadIdx.y; i < 32; i += 8)
        t[i][threadIdx.x] = Wd[(size_t)(k0 + i) * DIMK + n0 + threadIdx.x];
    __syncthreads();
    #pragma unroll
    for (int i = threadIdx.y; i < 32; i += 8) {
        const int k = k0 + threadIdx.x;
        const int n = n0 + i;
        float v = t[threadIdx.x][i] - ((k == n) ? 1.0f : 0.0f);
        g_Eh[((size_t)d * DIMK + n) * DIMK + k] = __float2half_rn(v);
    }
}

// xh = fp16(x), streaming convert (one float4 -> one 8B store per thread)
__global__ void __launch_bounds__(256, 8) prep_x_kernel(const float* __restrict__ x) {
    const size_t i = (size_t)blockIdx.x * blockDim.x + threadIdx.x;   // float4 index
    const float4 v = __ldg((const float4*)x + i);
    __half2 h0 = __float22half2_rn(make_float2(v.x, v.y));
    __half2 h1 = __float22half2_rn(make_float2(v.z, v.w));
    uint2 o;
    o.x = *(uint32_t*)&h0;
    o.y = *(uint32_t*)&h1;
    ((uint2*)g_xh)[i] = o;
}

// ---------------- main ----------------
__global__ void __launch_bounds__(NTHREADS, 2)
day_adapter_f16(const float* __restrict__ x,
                const int*   __restrict__ day_w,
                const float* __restrict__ bias,
                float*       __restrict__ out)
{
    extern __shared__ char smem[];
    const uint32_t sb = smem_u32(smem);
    const int tid  = threadIdx.x;
    const int wid  = tid >> 5;
    const int lane = tid & 31;

    const int n0   = blockIdx.x * CTA_N;
    const int m0   = blockIdx.y * CTA_M;
    const int bidx = blockIdx.z;

    const uint32_t mb_full  = sb;        // full[i] at sb + i*8
    const uint32_t mb_empty = sb + 64;   // empty[i] at sb + 64 + i*8
    if (tid == 0) {
        #pragma unroll
        for (int i = 0; i < STAGES; i++) {
            mbar_init(mb_full  + i * 8, NTHREADS);
            mbar_init(mb_empty + i * 8, NTHREADS);
        }
    }

    // robust day_ids decode (int32 vs int64 buffer)
    int is64 = 1;
    #pragma unroll 8
    for (int i = 1; i < 64; i += 2)
        if (__ldg(day_w + i) != 0) is64 = 0;
    const int day = is64 ? __ldg(day_w + 2 * bidx) : __ldg(day_w + bidx);

    __syncthreads();   // mbarrier init visible before any arrivals

    // -------- stage loaders: thread t -> row=t>>1, chunks (t&1)*2, +1 --------
    const int lrow = tid >> 1;
    const int lc0  = (tid & 1) * 2;
    const __half* agp = g_xh + ((size_t)bidx * TOK + m0 + lrow) * DIMK + lc0 * 8;
    const __half* bgp = g_Eh + ((size_t)day  * DIMK + n0 + lrow) * DIMK + lc0 * 8;
    const uint32_t lso0 = swz64(lrow, lc0), lso1 = swz64(lrow, lc0 + 1);

    auto LOAD_STAGE = [&](uint32_t stg, int s) {
        const __half* asrc = agp + s * BK;
        const __half* bsrc = bgp + s * BK;
        cp_async16(stg + OFF_A + lso0, asrc);
        cp_async16(stg + OFF_A + lso1, asrc + 8);
        cp_async16(stg + OFF_B + lso0, bsrc);
        cp_async16(stg + OFF_B + lso1, bsrc + 8);
    };

    // -------- warp tile: 2(m) x 4(n), 64x32 --------
    const int mw = (wid >> 2) * 64;
    const int nw = (wid & 3) * 32;
    const int kswap = wid & 1;               // odd warps traverse kg as 1,0

    float acc[4][4][4];
    #pragma unroll
    for (int i = 0; i < 4; i++)
        #pragma unroll
        for (int j = 0; j < 4; j++)
            #pragma unroll
            for (int q = 0; q < 4; q++) acc[i][j][q] = 0.0f;

    // ldmatrix lane addressing (fp16, 64B rows)
    const int a_row = mw + (lane & 15);                       // + mt*16
    const int a_ch  = lane >> 4;                              // + 2*kg
    const int b_row = nw + (lane & 7) + ((lane >> 4) << 3);   // + np*16
    const int b_ch  = (lane >> 3) & 1;                        // + 2*kg

    // -------- prolog: fill slots 0..2 --------
    LOAD_STAGE(sb + SM_TILES + 0 * STG_BYTES, 0);
    cp_mbar_arrive(mb_full + 0 * 8);
    LOAD_STAGE(sb + SM_TILES + 1 * STG_BYTES, 1);
    cp_mbar_arrive(mb_full + 1 * 8);
    LOAD_STAGE(sb + SM_TILES + 2 * STG_BYTES, 2);
    cp_mbar_arrive(mb_full + 2 * 8);

    int slotC = 0;                 // consume slot (stage s)
    int slotP = STAGES - 1;        // produce slot (stage s+STAGES-1)
    uint32_t phF = 0, phE = 0;     // phase bitmasks per slot

    // -------- main loop: mbarrier-paced, no CTA barrier --------
    #pragma unroll 1
    for (int s = 0; s < KSTEPS; s++) {
        const uint32_t stg  = sb + SM_TILES + slotC * STG_BYTES;
        const uint32_t stgA = stg + OFF_A;
        const uint32_t stgB = stg + OFF_B;

        mbar_wait(mb_full + slotC * 8, (phF >> slotC) & 1);
        phF ^= 1u << slotC;

        // fragment double buffers; preload first kg (= kswap)
        uint32_t bf[2][8];
        uint32_t af[2][4];
        ldsm_x4(bf[0] + 0, stgB + swz64(b_row,      2 * kswap + b_ch));
        ldsm_x4(bf[0] + 4, stgB + swz64(b_row + 16, 2 * kswap + b_ch));
        ldsm_x4(af[0],     stgA + swz64(a_row,      2 * kswap + a_ch));

        // producer: refill slotP for stage s+3
        if (s + STAGES - 1 < KSTEPS) {
            if (s > 0) {
                mbar_wait(mb_empty + slotP * 8, (phE >> slotP) & 1);
                phE ^= 1u << slotP;
            }
            LOAD_STAGE(sb + SM_TILES + slotP * STG_BYTES, s + STAGES - 1);
            cp_mbar_arrive(mb_full + slotP * 8);
        }

        int ab = 0;
        #pragma unroll
        for (int kg = 0; kg < 2; kg++) {
            const int cur = kg;
            const int kk  = kg ^ kswap;
            const int kkn = kk ^ 1;             // the other kg (next iteration's)
            if (kg < 1) {
                ldsm_x4(bf[1] + 0, stgB + swz64(b_row,      2 * kkn + b_ch));
                ldsm_x4(bf[1] + 4, stgB + swz64(b_row + 16, 2 * kkn + b_ch));
            }
            #pragma unroll
            for (int mt = 0; mt < 4; mt++) {
                if (mt < 3)
                    ldsm_x4(af[ab ^ 1], stgA + swz64(a_row + (mt + 1) * 16, 2 * kk + a_ch));
                else if (kg < 1)
                    ldsm_x4(af[ab ^ 1], stgA + swz64(a_row, 2 * kkn + a_ch));
                #pragma unroll
                for (int nt = 0; nt < 4; nt++)
                    mma_f16(acc[mt][nt], af[ab],
                            bf[cur][(nt >> 1) * 4 + (nt & 1) * 2],
                            bf[cur][(nt >> 1) * 4 + (nt & 1) * 2 + 1]);
                ab ^= 1;
            }
        }

        mbar_arrive(mb_empty + slotC * 8);

        slotC = (slotC == STAGES - 1) ? 0 : slotC + 1;
        slotP = (slotP == STAGES - 1) ? 0 : slotP + 1;
    }

    // -------- epilogue: y = x (exact fp32) + acc + bias; softsign --------
    const int r  = lane >> 2;
    const int cq = (lane & 3) * 2;
    const float* xep = x + (size_t)bidx * TOK * DIMK;
    const float* bp  = bias + (size_t)day * DIMK;

    #pragma unroll
    for (int nt = 0; nt < 4; nt++) {
        const int n = n0 + nw + nt * 8 + cq;
        const float2 bb = *(const float2*)(bp + n);
        #pragma unroll
        for (int mt = 0; mt < 4; mt++) {
            const int m = m0 + mw + mt * 16 + r;
            const float2 x0 = __ldg((const float2*)(xep + (size_t)m * DIMK + n));
            const float2 x1 = __ldg((const float2*)(xep + (size_t)(m + 8) * DIMK + n));
            float y0 = acc[mt][nt][0] + x0.x + bb.x;
            float y1 = acc[mt][nt][1] + x0.y + bb.y;
            float y2 = acc[mt][nt][2] + x1.x + bb.x;
            float y3 = acc[mt][nt][3] + x1.y + bb.y;
            float2 o0, o1;
            o0.x = __fdividef(y0, 1.0f + fabsf(y0));
            o0.y = __fdividef(y1, 1.0f + fabsf(y1));
            o1.x = __fdividef(y2, 1.0f + fabsf(y2));
            o1.y = __fdividef(y3, 1.0f + fabsf(y3));
            *(float2*)(out + (size_t)bidx * TOK * DIMK + (size_t)m * DIMK + n)       = o0;
            *(float2*)(out + (size_t)bidx * TOK * DIMK + (size_t)(m + 8) * DIMK + n) = o1;
        }
    }
}

// ---------------- launch ----------------
extern "C" void kernel_launch(void* const* d_in, const int* in_sizes, int n_in,
                              void* d_out, int out_size)
{
    const float* x   = (const float*)d_in[0];
    const int*   day = (const int*)  d_in[1];
    const float* W   = (const float*)d_in[2];
    const float* b   = (const float*)d_in[3];
    float*       out = (float*)d_out;

    cudaFuncSetAttribute(day_adapter_f16,
                         cudaFuncAttributeMaxDynamicSharedMemorySize, SMEM_TOTAL);

    prep_e_kernel<<<dim3(DIMK / 32, DIMK / 32, NDAYS), dim3(32, 8)>>>(W);

    const size_t n4 = (size_t)NB * TOK * DIMK / 4;     // float4 count = 8388608
    prep_x_kernel<<<(unsigned)(n4 / 256), 256>>>(x);

    dim3 grid(DIMK / CTA_N, TOK / CTA_M, NB);   // (4, 8, 64) = 2048 CTAs
    day_adapter_f16<<<grid, NTHREADS, SMEM_TOTAL>>>(x, day, b, out);
}